// round 10
// baseline (speedup 1.0000x reference)
#include <cuda_runtime.h>
#include <cuda_bf16.h>
#include <math.h>
#include <stdint.h>

// ---------------- problem constants ----------------
#define NC    8
#define HD    256
#define DIN   36
#define NMID  3
#define NMAX  65536
#define TM    64           // points per CTA
#define NTHR  256          // 8 warps: 2 (m) x 4 (n)

#define NKSTEP    51       // 3 (layer0 K=48) + 3*16 (mid layers K=256)
#define KSTEP_B   16384    // bytes per kstep: 2 splits x 4 wn x 4 jg x 512
#define CLUST_B   (NKSTEP * KSTEP_B)   // 835584 per cluster
#define AROW      528      // A SMEM row stride bytes (132 words, conflict-free)
#define HROW      264      // final fp32 hidden row stride (floats)

// SMEM layout (bytes)
#define SM_AHI   0
#define SM_ALO   (SM_AHI + TM * AROW)            // 33792
#define SM_BIAS  (SM_ALO + TM * AROW)            // 67584  (4*256 floats)
#define SM_WOUT  (SM_BIAS + 4 * HD * 4)          // 71680  (3*256 floats)
#define SM_BOUT  (SM_WOUT + 3 * HD * 4)          // 74752  (4 floats)
#define SM_IDX   (SM_BOUT + 16)                  // 74768  (64 ints)
#define SMEM_BYTES (SM_IDX + TM * 4)             // 75024

// prep kernel block ranges
#define NB_SCAT  256
#define NB_MID   768      // 6144 mid rows / 8 warps
#define NB_WIN   256      // 2048 win rows / 8 warps
#define NB_WOUT  1
#define NB_PREP  (NB_SCAT + NB_MID + NB_WIN + NB_WOUT)

// ---------------- device scratch ----------------
__device__ float d_Wout[NC * NMID * HD];
__device__ __align__(512) unsigned char d_Wpk[NC * CLUST_B];   // ~6.5 MB fragment-packed weights
__device__ int   d_sortedPad[NC * NMAX];
__device__ int   d_cursor[NC];
__device__ int   d_blkoff[NC + 1];

// ---------------- helpers ----------------
__device__ __forceinline__ void split_w(float w, __nv_bfloat16& hi, __nv_bfloat16& lo) {
    hi = __float2bfloat16(w);
    lo = __float2bfloat16(w - __bfloat162float(hi));
}

// fragment-packed address for weight element (cluster c, kstep s, split p, row r, kk in [0,16))
__device__ __forceinline__ size_t wpk_addr(int c, int s, int p, int r, int kk) {
    int wn  = r >> 6;
    int rr  = r & 63;
    int jg  = rr >> 4;
    int q8  = (rr >> 3) & 1;
    int gid = rr & 7;
    int kp  = kk >> 1;
    int tig = kp & 3;
    int wsl = kp >> 2;
    int lane = 4 * gid + tig;
    int w    = q8 * 2 + wsl;
    return (size_t)c * CLUST_B + (size_t)(((s * 2 + p) * 4 + wn) * 4 + jg) * 512
         + (size_t)lane * 16 + (size_t)w * 4 + (size_t)(kk & 1) * 2;
}

// ---------------- setup kernels ----------------
__global__ void initK() { if (threadIdx.x < NC) d_cursor[threadIdx.x] = 0; }

__global__ void prepK(const int* __restrict__ cid, int n,
                      const float* __restrict__ V_in,  const float* __restrict__ g_in,
                      const float* __restrict__ V_mid, const float* __restrict__ g_mid,
                      const float* __restrict__ V_out, const float* __restrict__ g_out) {
    const int blk  = blockIdx.x;
    const int tid  = threadIdx.x;
    const int wid  = tid >> 5;
    const int lane = tid & 31;

    if (blk < NB_SCAT) {
        __shared__ int lh[NC], base[NC];
        if (tid < NC) lh[tid] = 0;
        __syncthreads();
        int i = blk * 256 + tid;
        int c = -1, r = 0;
        if (i < n) { c = cid[i]; r = atomicAdd(&lh[c], 1); }
        __syncthreads();
        if (tid < NC) base[tid] = atomicAdd(&d_cursor[tid], lh[tid]);
        __syncthreads();
        if (i < n) d_sortedPad[c * NMAX + base[c] + r] = i;
        return;
    }
    if (blk < NB_SCAT + NB_MID) {
        // mid weights: norm + split-bf16 into fragment-packed blocks
        int row = (blk - NB_SCAT) * 8 + wid;         // [0, 6144)
        int c = row / (NMID * HD);
        int l = (row / HD) % NMID;
        int r = row & (HD - 1);
        const float* v = V_mid + (size_t)row * HD;
        float vals[8];
        float s = 0.f;
        #pragma unroll
        for (int j = 0; j < 8; j++) { vals[j] = v[lane + 32 * j]; s = fmaf(vals[j], vals[j], s); }
        #pragma unroll
        for (int off = 16; off; off >>= 1) s += __shfl_xor_sync(0xffffffffu, s, off);
        float scale = g_mid[row] * rsqrtf(s);
        #pragma unroll
        for (int j = 0; j < 8; j++) {
            float w = vals[j] * scale;
            __nv_bfloat16 hi, lo; split_w(w, hi, lo);
            int k = lane + 32 * j;
            int ks = 3 + l * 16 + (k >> 4);
            int kk = k & 15;
            *reinterpret_cast<__nv_bfloat16*>(d_Wpk + wpk_addr(c, ks, 0, r, kk)) = hi;
            *reinterpret_cast<__nv_bfloat16*>(d_Wpk + wpk_addr(c, ks, 1, r, kk)) = lo;
        }
        return;
    }
    if (blk < NB_SCAT + NB_MID + NB_WIN) {
        // layer-0 weights: norm + split-bf16, K padded 36 -> 48 (zeros)
        int row = (blk - NB_SCAT - NB_MID) * 8 + wid;   // [0, 2048)
        int c = row >> 8;
        int r = row & 255;
        const float* v = V_in + (size_t)row * DIN;
        float v0 = v[lane];
        float v1 = (lane < DIN - 32) ? v[32 + lane] : 0.f;
        float s = fmaf(v0, v0, v1 * v1);
        #pragma unroll
        for (int off = 16; off; off >>= 1) s += __shfl_xor_sync(0xffffffffu, s, off);
        float scale = g_in[row] * rsqrtf(s);
        #pragma unroll
        for (int half = 0; half < 2; half++) {
            int k = lane + 32 * half;
            if (k >= 48) continue;
            float w = (k < 32) ? v0 * scale : ((k < DIN) ? v1 * scale : 0.f);
            __nv_bfloat16 hi, lo; split_w(w, hi, lo);
            int ks = k >> 4;
            int kk = k & 15;
            *reinterpret_cast<__nv_bfloat16*>(d_Wpk + wpk_addr(c, ks, 0, r, kk)) = hi;
            *reinterpret_cast<__nv_bfloat16*>(d_Wpk + wpk_addr(c, ks, 1, r, kk)) = lo;
        }
        return;
    }
    {
        #pragma unroll
        for (int it = 0; it < 3; it++) {
            int row = wid * 3 + it;                    // [0, 24)
            const float* v = V_out + (size_t)row * HD;
            float vals[8];
            float s = 0.f;
            #pragma unroll
            for (int j = 0; j < 8; j++) { vals[j] = v[lane + 32 * j]; s = fmaf(vals[j], vals[j], s); }
            #pragma unroll
            for (int off = 16; off; off >>= 1) s += __shfl_xor_sync(0xffffffffu, s, off);
            float scale = g_out[row] * rsqrtf(s);
            #pragma unroll
            for (int j = 0; j < 8; j++) d_Wout[row * HD + lane + 32 * j] = vals[j] * scale;
        }
    }
}

__global__ void prefixK() {
    if (threadIdx.x == 0) {
        int bo = 0;
        for (int c = 0; c < NC; c++) {
            d_blkoff[c] = bo;
            bo += (d_cursor[c] + TM - 1) / TM;
        }
        d_blkoff[NC] = bo;
    }
}

// ---------------- PTX helpers ----------------
__device__ __forceinline__ void ldsm4(uint32_t& r0, uint32_t& r1, uint32_t& r2, uint32_t& r3, uint32_t a) {
    asm volatile("ldmatrix.sync.aligned.m8n8.x4.shared.b16 {%0,%1,%2,%3}, [%4];"
                 : "=r"(r0), "=r"(r1), "=r"(r2), "=r"(r3) : "r"(a));
}

__device__ __forceinline__ void mma16816(float* d, const uint32_t* a, uint32_t b0, uint32_t b1) {
    asm volatile("mma.sync.aligned.m16n8k16.row.col.f32.bf16.bf16.f32 "
                 "{%0,%1,%2,%3}, {%4,%5,%6,%7}, {%8,%9}, {%0,%1,%2,%3};"
                 : "+f"(d[0]), "+f"(d[1]), "+f"(d[2]), "+f"(d[3])
                 : "r"(a[0]), "r"(a[1]), "r"(a[2]), "r"(a[3]), "r"(b0), "r"(b1));
}

__device__ __forceinline__ uint32_t pack_hi(float a, float b, float& ra, float& rb) {
    __nv_bfloat16 ah = __float2bfloat16(a);
    __nv_bfloat16 bh = __float2bfloat16(b);
    ra = a - __bfloat162float(ah);
    rb = b - __bfloat162float(bh);
    __nv_bfloat162 h2 = __halves2bfloat162(ah, bh);
    return *reinterpret_cast<uint32_t*>(&h2);
}
__device__ __forceinline__ uint32_t pack_lo(float ra, float rb) {
    __nv_bfloat162 l2 = __floats2bfloat162_rn(ra, rb);
    return *reinterpret_cast<uint32_t*>(&l2);
}

// ---------------- fused MLP: all-MMA, B direct from L2 (no k-loop barriers) ----------------
__global__ void __launch_bounds__(NTHR, 2)
mlpK(const float* __restrict__ X,
     const float* __restrict__ b_in,
     const float* __restrict__ b_mid,
     const float* __restrict__ b_out,
     float* __restrict__ out, int n) {
    extern __shared__ unsigned char smem[];

    int b = blockIdx.x;
    if (b >= d_blkoff[NC]) return;
    int c = 0;
    while (b >= d_blkoff[c + 1]) c++;
    const int start = (b - d_blkoff[c]) * TM;
    int cnt = d_cursor[c] - start;
    if (cnt > TM) cnt = TM;
    if (cnt < 0) cnt = 0;

    const int tid  = threadIdx.x;
    const int wid  = tid >> 5;
    const int lane = tid & 31;
    const int gid  = lane >> 2;
    const int tig  = lane & 3;
    const int sel  = lane >> 3;
    const int r8   = lane & 7;
    const uint32_t sbase = (uint32_t)__cvta_generic_to_shared(smem);

    float* biasS = (float*)(smem + SM_BIAS);
    float* WoutS = (float*)(smem + SM_WOUT);
    float* boutS = (float*)(smem + SM_BOUT);
    int*   idxS  = (int*)  (smem + SM_IDX);

    // ---- stage biases / Wout / bout ----
    #pragma unroll
    for (int it = 0; it < 4; it++) {
        int s = tid + it * NTHR;            // [0,1024)
        float v;
        if (s < HD) v = b_in[c * HD + s];
        else        v = b_mid[(c * NMID + (s / HD - 1)) * HD + (s & (HD - 1))];
        biasS[s] = v;
    }
    #pragma unroll
    for (int it = 0; it < 3; it++) {
        int s = tid + it * NTHR;
        WoutS[s] = d_Wout[c * NMID * HD + s];
    }
    if (tid < 3) boutS[tid] = b_out[c * NMID + tid];

    // ---- posenc -> split-bf16 A image (K padded to 48) ----
    if (tid < TM) {
        const int m = tid;
        const int id = (m < cnt) ? d_sortedPad[c * NMAX + start + m] : -1;
        idxS[m] = id;
        float e[36];
        #pragma unroll
        for (int k = 0; k < 36; k++) e[k] = 0.f;
        if (id >= 0) {
            float x = X[3 * id], y = X[3 * id + 1], z = X[3 * id + 2];
            float f = 1.f;
            #pragma unroll
            for (int fi = 0; fi < 6; fi++) {
                float s0, c0, s1, c1, s2, c2;
                sincosf(x * f, &s0, &c0);
                sincosf(y * f, &s1, &c1);
                sincosf(z * f, &s2, &c2);
                e[fi * 6 + 0] = s0; e[fi * 6 + 1] = s1; e[fi * 6 + 2] = s2;
                e[fi * 6 + 3] = c0; e[fi * 6 + 4] = c1; e[fi * 6 + 5] = c2;
                f *= 2.f;
            }
        }
        uint32_t* hi = (uint32_t*)(smem + SM_AHI + m * AROW);
        uint32_t* lo = (uint32_t*)(smem + SM_ALO + m * AROW);
        #pragma unroll
        for (int i = 0; i < 18; i++) {
            float ra, rb;
            hi[i] = pack_hi(e[2 * i], e[2 * i + 1], ra, rb);
            lo[i] = pack_lo(ra, rb);
        }
        #pragma unroll
        for (int i = 18; i < 24; i++) { hi[i] = 0u; lo[i] = 0u; }
    }
    __syncthreads();

    // warp tiling: 2 (m) x 4 (n)
    const int m_base = (wid & 1) * 32;
    const int wn     = wid >> 1;        // n group, n_base = wn*64
    const int n_base = wn * 64;

    uint32_t a_off[2];
    #pragma unroll
    for (int im = 0; im < 2; im++)
        a_off[im] = (uint32_t)((m_base + im * 16 + r8 + (sel & 1) * 8) * AROW + (sel >> 1) * 16);

    // B fragment base: per (kstep s, split p, jg): wsrc + ((s*2+p)*16 + wn*4 + jg)*512 + lane*16
    const unsigned char* wsrc = d_Wpk + (size_t)c * CLUST_B
                              + (size_t)(wn * 4) * 512 + (size_t)lane * 16;

    #pragma unroll 1
    for (int l = 0; l < 4; l++) {
        float D[2][8][4];
        #pragma unroll
        for (int im = 0; im < 2; im++)
            #pragma unroll
            for (int jn = 0; jn < 8; jn++)
                #pragma unroll
                for (int e = 0; e < 4; e++) D[im][jn][e] = 0.f;

        const int ksbase = (l == 0) ? 0 : 3 + (l - 1) * 16;
        const int nk     = (l == 0) ? 3 : 16;

        #pragma unroll 2
        for (int t = 0; t < nk; t++) {
            const int s = ksbase + t;
            const unsigned char* kb = wsrc + (size_t)s * KSTEP_B;

            // ---- issue all B loads for this kstep (L2-resident, .nc cached) ----
            uint4 BH[4], BL[4];
            #pragma unroll
            for (int jg = 0; jg < 4; jg++)
                BH[jg] = __ldg((const uint4*)(kb + (size_t)jg * 512));
            #pragma unroll
            for (int jg = 0; jg < 4; jg++)
                BL[jg] = __ldg((const uint4*)(kb + 8192 + (size_t)jg * 512));

            // ---- A fragments via ldmatrix (hi + lo) ----
            const uint32_t kbA = (uint32_t)t * 32;
            uint32_t Ahi[2][4], Alo[2][4];
            #pragma unroll
            for (int im = 0; im < 2; im++) {
                ldsm4(Ahi[im][0], Ahi[im][1], Ahi[im][2], Ahi[im][3],
                      sbase + SM_AHI + a_off[im] + kbA);
                ldsm4(Alo[im][0], Alo[im][1], Alo[im][2], Alo[im][3],
                      sbase + SM_ALO + a_off[im] + kbA);
            }

            // s0: Ahi x Bhi
            #pragma unroll
            for (int jg = 0; jg < 4; jg++)
                #pragma unroll
                for (int im = 0; im < 2; im++) {
                    mma16816(D[im][jg * 2],     Ahi[im], BH[jg].x, BH[jg].y);
                    mma16816(D[im][jg * 2 + 1], Ahi[im], BH[jg].z, BH[jg].w);
                }
            // s1: Alo x Bhi
            #pragma unroll
            for (int jg = 0; jg < 4; jg++)
                #pragma unroll
                for (int im = 0; im < 2; im++) {
                    mma16816(D[im][jg * 2],     Alo[im], BH[jg].x, BH[jg].y);
                    mma16816(D[im][jg * 2 + 1], Alo[im], BH[jg].z, BH[jg].w);
                }
            // s2: Ahi x Blo
            #pragma unroll
            for (int jg = 0; jg < 4; jg++)
                #pragma unroll
                for (int im = 0; im < 2; im++) {
                    mma16816(D[im][jg * 2],     Ahi[im], BL[jg].x, BL[jg].y);
                    mma16816(D[im][jg * 2 + 1], Ahi[im], BL[jg].z, BL[jg].w);
                }
        }

        // ---- epilogue: barrier (all warps done reading A), rewrite A, barrier ----
        __syncthreads();
        const float* bias = biasS + l * HD;
        if (l < 3) {
            #pragma unroll
            for (int im = 0; im < 2; im++) {
                #pragma unroll
                for (int jn = 0; jn < 8; jn++) {
                    int ncol = n_base + jn * 8 + tig * 2;
                    float b0 = bias[ncol], b1 = bias[ncol + 1];
                    #pragma unroll
                    for (int h = 0; h < 2; h++) {
                        int m = m_base + im * 16 + gid + h * 8;
                        float v0 = fmaxf(D[im][jn][2 * h]     + b0, 0.f);
                        float v1 = fmaxf(D[im][jn][2 * h + 1] + b1, 0.f);
                        float ra, rb;
                        uint32_t ph = pack_hi(v0, v1, ra, rb);
                        uint32_t pl = pack_lo(ra, rb);
                        *(uint32_t*)(smem + SM_AHI + m * AROW + ncol * 2) = ph;
                        *(uint32_t*)(smem + SM_ALO + m * AROW + ncol * 2) = pl;
                    }
                }
            }
            __syncthreads();
        } else {
            // final hidden -> fp32 h in A region (HROW floats per row)
            float* hbuf = (float*)(smem + SM_AHI);
            #pragma unroll
            for (int im = 0; im < 2; im++) {
                #pragma unroll
                for (int jn = 0; jn < 8; jn++) {
                    int ncol = n_base + jn * 8 + tig * 2;
                    float b0 = bias[ncol], b1 = bias[ncol + 1];
                    #pragma unroll
                    for (int h = 0; h < 2; h++) {
                        int m = m_base + im * 16 + gid + h * 8;
                        float v0 = fmaxf(D[im][jn][2 * h]     + b0, 0.f);
                        float v1 = fmaxf(D[im][jn][2 * h + 1] + b1, 0.f);
                        float2* p = (float2*)(hbuf + m * HROW + ncol);
                        *p = make_float2(v0, v1);
                    }
                }
            }
            __syncthreads();
            // fused output layer: 192 (m,j) dots of length 256
            const float* hb = (const float*)(smem + SM_AHI);
            #pragma unroll
            for (int qq = 0; qq < 24; qq++) {
                int o = wid * 24 + qq;
                int m = o / 3, j = o - 3 * m;
                const float* hr = hb + m * HROW;
                const float* wr = WoutS + j * HD;
                float s = 0.f;
                #pragma unroll
                for (int k = lane; k < HD; k += 32) s = fmaf(hr[k], wr[k], s);
                #pragma unroll
                for (int off = 16; off; off >>= 1) s += __shfl_xor_sync(0xffffffffu, s, off);
                if (lane == 0) {
                    int id = idxS[m];
                    if (id >= 0) out[3 * id + j] = tanhf(s + boutS[j]);
                }
            }
        }
    }
}

// ---------------- launch ----------------
extern "C" void kernel_launch(void* const* d_in, const int* in_sizes, int n_in,
                              void* d_out, int out_size) {
    const float* X     = (const float*)d_in[0];
    const int*   cid   = (const int*)  d_in[1];
    const float* V_in  = (const float*)d_in[2];
    const float* g_in  = (const float*)d_in[3];
    const float* b_in  = (const float*)d_in[4];
    const float* V_mid = (const float*)d_in[5];
    const float* g_mid = (const float*)d_in[6];
    const float* b_mid = (const float*)d_in[7];
    const float* V_out = (const float*)d_in[8];
    const float* g_out = (const float*)d_in[9];
    const float* b_out = (const float*)d_in[10];
    float* out = (float*)d_out;
    const int n = in_sizes[0] / 3;

    cudaFuncSetAttribute(mlpK, cudaFuncAttributeMaxDynamicSharedMemorySize, SMEM_BYTES);

    initK<<<1, 32>>>();
    prepK<<<NB_PREP, 256>>>(cid, n, V_in, g_in, V_mid, g_mid, V_out, g_out);
    prefixK<<<1, 1>>>();

    const int blocks = (n + TM - 1) / TM + NC;
    mlpK<<<blocks, NTHR, SMEM_BYTES>>>(X, b_in, b_mid, b_out, out, n);
}

// round 11
// speedup vs baseline: 1.3601x; 1.3601x over previous
#include <cuda_runtime.h>
#include <cuda_bf16.h>
#include <math.h>
#include <stdint.h>

// ---------------- problem constants ----------------
#define NC    8
#define HD    256
#define DIN   36
#define NMID  3
#define NMAX  65536
#define TM    64           // points per CTA
#define NTHR  256          // 8 warps: 2 (m) x 4 (n)

#define BROW2     48       // hi chunk row stride bytes (12 words, conflict-free ldmatrix)
#define CHUNK2    12288    // 256 rows x 48B: one kstep, hi split
#define NRING     3
#define NKSTEP    51       // 3 (layer0 K=48) + 3*16 (mid layers K=256)
#define LO_KB     8192     // lo split per kstep: 4 wn x 4 jg x 512B (fragment-packed, LDG path)
#define AROW      528      // A SMEM row stride bytes (132 words, conflict-free)
#define HROW      264      // final fp32 hidden row stride (floats)

// SMEM layout (bytes)
#define SM_AHI   0
#define SM_ALO   (SM_AHI + TM * AROW)            // 33792
#define SM_B     (SM_ALO + TM * AROW)            // 67584  (ring: 3 x 12288)
#define SM_BIAS  (SM_B + NRING * CHUNK2)         // 104448 (4*256 floats)
#define SM_WOUT  (SM_BIAS + 4 * HD * 4)          // 108544 (3*256 floats)
#define SM_BOUT  (SM_WOUT + 3 * HD * 4)          // 111616
#define SM_IDX   (SM_BOUT + 16)                  // 111632
#define SMEM_BYTES (SM_IDX + TM * 4)             // 111888  (2 CTAs/SM fits)

// prep kernel block ranges
#define NB_SCAT  256
#define NB_MID   768      // 6144 mid rows / 8 warps
#define NB_WIN   256      // 2048 win rows / 8 warps
#define NB_WOUT  1
#define NB_PREP  (NB_SCAT + NB_MID + NB_WIN + NB_WOUT)

// ---------------- device scratch ----------------
__device__ float d_Wout[NC * NMID * HD];
__device__ __align__(512) unsigned char d_WpkHi[NC * NKSTEP * CHUNK2];  // ~5.0 MB SMEM-image hi
__device__ __align__(512) unsigned char d_WpkLo[NC * NKSTEP * LO_KB];   // ~3.3 MB fragment-packed lo
__device__ int   d_sortedPad[NC * NMAX];
__device__ int   d_cursor[NC];
__device__ int   d_blkoff[NC + 1];

// ---------------- helpers ----------------
__device__ __forceinline__ void split_w(float w, __nv_bfloat16& hi, __nv_bfloat16& lo) {
    hi = __float2bfloat16(w);
    lo = __float2bfloat16(w - __bfloat162float(hi));
}

// fragment-packed lo address (validated in round 10): element (cluster c, kstep s, row r, kk)
__device__ __forceinline__ size_t wlo_addr(int c, int s, int r, int kk) {
    int wn  = r >> 6;
    int rr  = r & 63;
    int jg  = rr >> 4;
    int q8  = (rr >> 3) & 1;
    int gid = rr & 7;
    int kp  = kk >> 1;
    int tig = kp & 3;
    int wsl = kp >> 2;
    int lane = 4 * gid + tig;
    int w    = q8 * 2 + wsl;
    return (size_t)(c * NKSTEP + s) * LO_KB + (size_t)(wn * 4 + jg) * 512
         + (size_t)lane * 16 + (size_t)w * 4 + (size_t)(kk & 1) * 2;
}

// ---------------- setup kernels ----------------
__global__ void initK() { if (threadIdx.x < NC) d_cursor[threadIdx.x] = 0; }

__global__ void prepK(const int* __restrict__ cid, int n,
                      const float* __restrict__ V_in,  const float* __restrict__ g_in,
                      const float* __restrict__ V_mid, const float* __restrict__ g_mid,
                      const float* __restrict__ V_out, const float* __restrict__ g_out) {
    const int blk  = blockIdx.x;
    const int tid  = threadIdx.x;
    const int wid  = tid >> 5;
    const int lane = tid & 31;

    if (blk < NB_SCAT) {
        __shared__ int lh[NC], base[NC];
        if (tid < NC) lh[tid] = 0;
        __syncthreads();
        int i = blk * 256 + tid;
        int c = -1, r = 0;
        if (i < n) { c = cid[i]; r = atomicAdd(&lh[c], 1); }
        __syncthreads();
        if (tid < NC) base[tid] = atomicAdd(&d_cursor[tid], lh[tid]);
        __syncthreads();
        if (i < n) d_sortedPad[c * NMAX + base[c] + r] = i;
        return;
    }
    if (blk < NB_SCAT + NB_MID) {
        // mid weights: norm + split; hi -> SMEM-image chunks, lo -> fragment-packed
        int row = (blk - NB_SCAT) * 8 + wid;         // [0, 6144)
        int c = row / (NMID * HD);
        int l = (row / HD) % NMID;
        int r = row & (HD - 1);
        const float* v = V_mid + (size_t)row * HD;
        float vals[8];
        float s = 0.f;
        #pragma unroll
        for (int j = 0; j < 8; j++) { vals[j] = v[lane + 32 * j]; s = fmaf(vals[j], vals[j], s); }
        #pragma unroll
        for (int off = 16; off; off >>= 1) s += __shfl_xor_sync(0xffffffffu, s, off);
        float scale = g_mid[row] * rsqrtf(s);
        #pragma unroll
        for (int j = 0; j < 8; j++) {
            float w = vals[j] * scale;
            __nv_bfloat16 hi, lo; split_w(w, hi, lo);
            int k = lane + 32 * j;
            int ks = 3 + l * 16 + (k >> 4);
            int kk = k & 15;
            size_t bh = (size_t)(c * NKSTEP + ks) * CHUNK2 + (size_t)r * BROW2 + (size_t)kk * 2;
            *reinterpret_cast<__nv_bfloat16*>(d_WpkHi + bh) = hi;
            *reinterpret_cast<__nv_bfloat16*>(d_WpkLo + wlo_addr(c, ks, r, kk)) = lo;
        }
        return;
    }
    if (blk < NB_SCAT + NB_MID + NB_WIN) {
        // layer-0 weights: norm + split, K padded 36 -> 48 (zeros)
        int row = (blk - NB_SCAT - NB_MID) * 8 + wid;   // [0, 2048)
        int c = row >> 8;
        int r = row & 255;
        const float* v = V_in + (size_t)row * DIN;
        float v0 = v[lane];
        float v1 = (lane < DIN - 32) ? v[32 + lane] : 0.f;
        float s = fmaf(v0, v0, v1 * v1);
        #pragma unroll
        for (int off = 16; off; off >>= 1) s += __shfl_xor_sync(0xffffffffu, s, off);
        float scale = g_in[row] * rsqrtf(s);
        #pragma unroll
        for (int half = 0; half < 2; half++) {
            int k = lane + 32 * half;
            if (k >= 48) continue;
            float w = (k < 32) ? v0 * scale : ((k < DIN) ? v1 * scale : 0.f);
            __nv_bfloat16 hi, lo; split_w(w, hi, lo);
            int ks = k >> 4;
            int kk = k & 15;
            size_t bh = (size_t)(c * NKSTEP + ks) * CHUNK2 + (size_t)r * BROW2 + (size_t)kk * 2;
            *reinterpret_cast<__nv_bfloat16*>(d_WpkHi + bh) = hi;
            *reinterpret_cast<__nv_bfloat16*>(d_WpkLo + wlo_addr(c, ks, r, kk)) = lo;
        }
        return;
    }
    {
        #pragma unroll
        for (int it = 0; it < 3; it++) {
            int row = wid * 3 + it;                    // [0, 24)
            const float* v = V_out + (size_t)row * HD;
            float vals[8];
            float s = 0.f;
            #pragma unroll
            for (int j = 0; j < 8; j++) { vals[j] = v[lane + 32 * j]; s = fmaf(vals[j], vals[j], s); }
            #pragma unroll
            for (int off = 16; off; off >>= 1) s += __shfl_xor_sync(0xffffffffu, s, off);
            float scale = g_out[row] * rsqrtf(s);
            #pragma unroll
            for (int j = 0; j < 8; j++) d_Wout[row * HD + lane + 32 * j] = vals[j] * scale;
        }
    }
}

__global__ void prefixK() {
    if (threadIdx.x == 0) {
        int bo = 0;
        for (int c = 0; c < NC; c++) {
            d_blkoff[c] = bo;
            bo += (d_cursor[c] + TM - 1) / TM;
        }
        d_blkoff[NC] = bo;
    }
}

// ---------------- PTX helpers ----------------
__device__ __forceinline__ void cp16(uint32_t s, const void* g) {
    asm volatile("cp.async.cg.shared.global [%0], [%1], 16;" :: "r"(s), "l"(g));
}
__device__ __forceinline__ void cp_commit()  { asm volatile("cp.async.commit_group;"); }
__device__ __forceinline__ void cp_wait1()   { asm volatile("cp.async.wait_group 1;" ::: "memory"); }

__device__ __forceinline__ void ldsm4(uint32_t& r0, uint32_t& r1, uint32_t& r2, uint32_t& r3, uint32_t a) {
    asm volatile("ldmatrix.sync.aligned.m8n8.x4.shared.b16 {%0,%1,%2,%3}, [%4];"
                 : "=r"(r0), "=r"(r1), "=r"(r2), "=r"(r3) : "r"(a));
}

__device__ __forceinline__ void mma16816(float* d, const uint32_t* a, uint32_t b0, uint32_t b1) {
    asm volatile("mma.sync.aligned.m16n8k16.row.col.f32.bf16.bf16.f32 "
                 "{%0,%1,%2,%3}, {%4,%5,%6,%7}, {%8,%9}, {%0,%1,%2,%3};"
                 : "+f"(d[0]), "+f"(d[1]), "+f"(d[2]), "+f"(d[3])
                 : "r"(a[0]), "r"(a[1]), "r"(a[2]), "r"(a[3]), "r"(b0), "r"(b1));
}

__device__ __forceinline__ uint32_t pack_hi(float a, float b, float& ra, float& rb) {
    __nv_bfloat16 ah = __float2bfloat16(a);
    __nv_bfloat16 bh = __float2bfloat16(b);
    ra = a - __bfloat162float(ah);
    rb = b - __bfloat162float(bh);
    __nv_bfloat162 h2 = __halves2bfloat162(ah, bh);
    return *reinterpret_cast<uint32_t*>(&h2);
}
__device__ __forceinline__ uint32_t pack_lo(float ra, float rb) {
    __nv_bfloat162 l2 = __floats2bfloat162_rn(ra, rb);
    return *reinterpret_cast<uint32_t*>(&l2);
}

// ---------------- fused MLP: hi via cp.async ring, lo via LDG; 1 barrier/kstep ----------------
__global__ void __launch_bounds__(NTHR, 2)
mlpK(const float* __restrict__ X,
     const float* __restrict__ b_in,
     const float* __restrict__ b_mid,
     const float* __restrict__ b_out,
     float* __restrict__ out, int n) {
    extern __shared__ unsigned char smem[];

    int b = blockIdx.x;
    if (b >= d_blkoff[NC]) return;
    int c = 0;
    while (b >= d_blkoff[c + 1]) c++;
    const int start = (b - d_blkoff[c]) * TM;
    int cnt = d_cursor[c] - start;
    if (cnt > TM) cnt = TM;
    if (cnt < 0) cnt = 0;

    const int tid  = threadIdx.x;
    const int wid  = tid >> 5;
    const int lane = tid & 31;
    const int gid  = lane >> 2;
    const int tig  = lane & 3;
    const int sel  = lane >> 3;
    const int r8   = lane & 7;
    const uint32_t sbase = (uint32_t)__cvta_generic_to_shared(smem);

    float* biasS = (float*)(smem + SM_BIAS);
    float* WoutS = (float*)(smem + SM_WOUT);
    float* boutS = (float*)(smem + SM_BOUT);
    int*   idxS  = (int*)  (smem + SM_IDX);

    // ---- stage biases / Wout / bout ----
    #pragma unroll
    for (int it = 0; it < 4; it++) {
        int s = tid + it * NTHR;            // [0,1024)
        float v;
        if (s < HD) v = b_in[c * HD + s];
        else        v = b_mid[(c * NMID + (s / HD - 1)) * HD + (s & (HD - 1))];
        biasS[s] = v;
    }
    #pragma unroll
    for (int it = 0; it < 3; it++) {
        int s = tid + it * NTHR;
        WoutS[s] = d_Wout[c * NMID * HD + s];
    }
    if (tid < 3) boutS[tid] = b_out[c * NMID + tid];

    // ---- posenc -> split-bf16 A image (K padded to 48) ----
    if (tid < TM) {
        const int m = tid;
        const int id = (m < cnt) ? d_sortedPad[c * NMAX + start + m] : -1;
        idxS[m] = id;
        float e[36];
        #pragma unroll
        for (int k = 0; k < 36; k++) e[k] = 0.f;
        if (id >= 0) {
            float x = X[3 * id], y = X[3 * id + 1], z = X[3 * id + 2];
            float f = 1.f;
            #pragma unroll
            for (int fi = 0; fi < 6; fi++) {
                float s0, c0, s1, c1, s2, c2;
                sincosf(x * f, &s0, &c0);
                sincosf(y * f, &s1, &c1);
                sincosf(z * f, &s2, &c2);
                e[fi * 6 + 0] = s0; e[fi * 6 + 1] = s1; e[fi * 6 + 2] = s2;
                e[fi * 6 + 3] = c0; e[fi * 6 + 4] = c1; e[fi * 6 + 5] = c2;
                f *= 2.f;
            }
        }
        uint32_t* hi = (uint32_t*)(smem + SM_AHI + m * AROW);
        uint32_t* lo = (uint32_t*)(smem + SM_ALO + m * AROW);
        #pragma unroll
        for (int i = 0; i < 18; i++) {
            float ra, rb;
            hi[i] = pack_hi(e[2 * i], e[2 * i + 1], ra, rb);
            lo[i] = pack_lo(ra, rb);
        }
        #pragma unroll
        for (int i = 18; i < 24; i++) { hi[i] = 0u; lo[i] = 0u; }
    }

    // warp tiling: 2 (m) x 4 (n)
    const int m_base = (wid & 1) * 32;
    const int wn     = wid >> 1;
    const int n_base = wn * 64;

    uint32_t a_off[2];
    #pragma unroll
    for (int im = 0; im < 2; im++)
        a_off[im] = (uint32_t)((m_base + im * 16 + r8 + (sel & 1) * 8) * AROW + (sel >> 1) * 16);
    uint32_t bg_off[4];
    #pragma unroll
    for (int jg = 0; jg < 4; jg++)
        bg_off[jg] = (uint32_t)((n_base + jg * 16 + r8 + (sel >> 1) * 8) * BROW2 + (sel & 1) * 16);

    const unsigned char* wHi = d_WpkHi + (size_t)c * NKSTEP * CHUNK2;
    const unsigned char* wLo = d_WpkLo + (size_t)c * NKSTEP * LO_KB
                             + (size_t)(wn * 4) * 512 + (size_t)lane * 16;

    // prefetch hi chunks 0, 1 into ring slots 0, 1
    #pragma unroll
    for (int pc = 0; pc < 2; pc++) {
        const unsigned char* g = wHi + (size_t)pc * CHUNK2;
        uint32_t sb = sbase + SM_B + pc * CHUNK2;
        #pragma unroll
        for (int j = 0; j < 3; j++) {
            int o = tid * 16 + j * 4096;
            cp16(sb + o, g + o);
        }
        cp_commit();
    }

    int q = 0;   // global kstep index

    #pragma unroll 1
    for (int l = 0; l < 4; l++) {
        float D[2][8][4];
        #pragma unroll
        for (int im = 0; im < 2; im++)
            #pragma unroll
            for (int jn = 0; jn < 8; jn++)
                #pragma unroll
                for (int e = 0; e < 4; e++) D[im][jn][e] = 0.f;

        const int nk = (l == 0) ? 3 : 16;
        #pragma unroll 1
        for (int t = 0; t < nk; t++) {
            cp_wait1();
            __syncthreads();

            // prefetch hi chunk q+2 into slot freed at q-1
            if (q + 2 < NKSTEP) {
                const unsigned char* g = wHi + (size_t)(q + 2) * CHUNK2;
                uint32_t sb = sbase + SM_B + ((q + 2) % NRING) * CHUNK2;
                #pragma unroll
                for (int j = 0; j < 3; j++) {
                    int o = tid * 16 + j * 4096;
                    cp16(sb + o, g + o);
                }
            }
            cp_commit();

            // issue B-lo LDGs now (consumed in s2, after 16 MMAs hide L2 latency)
            uint4 BL[4];
            {
                const unsigned char* kb = wLo + (size_t)q * LO_KB;
                #pragma unroll
                for (int jg = 0; jg < 4; jg++)
                    BL[jg] = __ldg((const uint4*)(kb + (size_t)jg * 512));
            }

            // A fragments via ldmatrix (hi + lo)
            const uint32_t kbA = (uint32_t)t * 32;
            uint32_t Ahi[2][4], Alo[2][4];
            #pragma unroll
            for (int im = 0; im < 2; im++) {
                ldsm4(Ahi[im][0], Ahi[im][1], Ahi[im][2], Ahi[im][3],
                      sbase + SM_AHI + a_off[im] + kbA);
                ldsm4(Alo[im][0], Alo[im][1], Alo[im][2], Alo[im][3],
                      sbase + SM_ALO + a_off[im] + kbA);
            }

            // B-hi via ldmatrix from ring slot
            const uint32_t bA = sbase + SM_B + (uint32_t)(q % NRING) * CHUNK2;
            uint32_t BH[4][4];
            #pragma unroll
            for (int jg = 0; jg < 4; jg++)
                ldsm4(BH[jg][0], BH[jg][1], BH[jg][2], BH[jg][3], bA + bg_off[jg]);

            // s0: Ahi x Bhi
            #pragma unroll
            for (int jg = 0; jg < 4; jg++)
                #pragma unroll
                for (int im = 0; im < 2; im++) {
                    mma16816(D[im][jg * 2],     Ahi[im], BH[jg][0], BH[jg][1]);
                    mma16816(D[im][jg * 2 + 1], Ahi[im], BH[jg][2], BH[jg][3]);
                }
            // s1: Alo x Bhi
            #pragma unroll
            for (int jg = 0; jg < 4; jg++)
                #pragma unroll
                for (int im = 0; im < 2; im++) {
                    mma16816(D[im][jg * 2],     Alo[im], BH[jg][0], BH[jg][1]);
                    mma16816(D[im][jg * 2 + 1], Alo[im], BH[jg][2], BH[jg][3]);
                }
            // s2: Ahi x Blo (LDG results, latency hidden under s0/s1)
            #pragma unroll
            for (int jg = 0; jg < 4; jg++)
                #pragma unroll
                for (int im = 0; im < 2; im++) {
                    mma16816(D[im][jg * 2],     Ahi[im], BL[jg].x, BL[jg].y);
                    mma16816(D[im][jg * 2 + 1], Ahi[im], BL[jg].z, BL[jg].w);
                }
            q++;
        }

        // ---- epilogue ----
        __syncthreads();
        const float* bias = biasS + l * HD;
        if (l < 3) {
            #pragma unroll
            for (int im = 0; im < 2; im++) {
                #pragma unroll
                for (int jn = 0; jn < 8; jn++) {
                    int ncol = n_base + jn * 8 + tig * 2;
                    float b0 = bias[ncol], b1 = bias[ncol + 1];
                    #pragma unroll
                    for (int h = 0; h < 2; h++) {
                        int m = m_base + im * 16 + gid + h * 8;
                        float v0 = fmaxf(D[im][jn][2 * h]     + b0, 0.f);
                        float v1 = fmaxf(D[im][jn][2 * h + 1] + b1, 0.f);
                        float ra, rb;
                        uint32_t ph = pack_hi(v0, v1, ra, rb);
                        uint32_t pl = pack_lo(ra, rb);
                        *(uint32_t*)(smem + SM_AHI + m * AROW + ncol * 2) = ph;
                        *(uint32_t*)(smem + SM_ALO + m * AROW + ncol * 2) = pl;
                    }
                }
            }
        } else {
            // final hidden -> fp32 h in A region (HROW floats per row)
            float* hbuf = (float*)(smem + SM_AHI);
            #pragma unroll
            for (int im = 0; im < 2; im++) {
                #pragma unroll
                for (int jn = 0; jn < 8; jn++) {
                    int ncol = n_base + jn * 8 + tig * 2;
                    float b0 = bias[ncol], b1 = bias[ncol + 1];
                    #pragma unroll
                    for (int h = 0; h < 2; h++) {
                        int m = m_base + im * 16 + gid + h * 8;
                        float v0 = fmaxf(D[im][jn][2 * h]     + b0, 0.f);
                        float v1 = fmaxf(D[im][jn][2 * h + 1] + b1, 0.f);
                        float2* p = (float2*)(hbuf + m * HROW + ncol);
                        *p = make_float2(v0, v1);
                    }
                }
            }
            __syncthreads();
            // fused output layer: 192 (m,j) dots of length 256
            const float* hb = (const float*)(smem + SM_AHI);
            #pragma unroll
            for (int qq = 0; qq < 24; qq++) {
                int o = wid * 24 + qq;
                int m = o / 3, j = o - 3 * m;
                const float* hr = hb + m * HROW;
                const float* wr = WoutS + j * HD;
                float s = 0.f;
                #pragma unroll
                for (int k = lane; k < HD; k += 32) s = fmaf(hr[k], wr[k], s);
                #pragma unroll
                for (int off = 16; off; off >>= 1) s += __shfl_xor_sync(0xffffffffu, s, off);
                if (lane == 0) {
                    int id = idxS[m];
                    if (id >= 0) out[3 * id + j] = tanhf(s + boutS[j]);
                }
            }
        }
    }
}

// ---------------- launch ----------------
extern "C" void kernel_launch(void* const* d_in, const int* in_sizes, int n_in,
                              void* d_out, int out_size) {
    const float* X     = (const float*)d_in[0];
    const int*   cid   = (const int*)  d_in[1];
    const float* V_in  = (const float*)d_in[2];
    const float* g_in  = (const float*)d_in[3];
    const float* b_in  = (const float*)d_in[4];
    const float* V_mid = (const float*)d_in[5];
    const float* g_mid = (const float*)d_in[6];
    const float* b_mid = (const float*)d_in[7];
    const float* V_out = (const float*)d_in[8];
    const float* g_out = (const float*)d_in[9];
    const float* b_out = (const float*)d_in[10];
    float* out = (float*)d_out;
    const int n = in_sizes[0] / 3;

    cudaFuncSetAttribute(mlpK, cudaFuncAttributeMaxDynamicSharedMemorySize, SMEM_BYTES);

    initK<<<1, 32>>>();
    prepK<<<NB_PREP, 256>>>(cid, n, V_in, g_in, V_mid, g_mid, V_out, g_out);
    prefixK<<<1, 1>>>();

    const int blocks = (n + TM - 1) / TM + NC;
    mlpK<<<blocks, NTHR, SMEM_BYTES>>>(X, b_in, b_mid, b_out, out, n);
}

// round 12
// speedup vs baseline: 2.7164x; 1.9972x over previous
#include <cuda_runtime.h>
#include <cuda_fp16.h>
#include <math.h>
#include <stdint.h>

// ---------------- problem constants ----------------
#define NC    8
#define HD    256
#define DIN   36
#define NMID  3
#define NMAX  65536
#define TM    64           // points per CTA
#define NTHR  256          // 8 warps: 2 (m) x 4 (n)

#define BROW2     48       // chunk row stride bytes (16 fp16 = 32B + 16B pad, conflict-free)
#define CHUNK2    12288    // 256 rows x 48B: one kstep of fp16 weights
#define NRING     4
#define NKSTEP    52       // 4 (layer0 K=64 padded) + 3*16 (mid layers K=256)
#define AROW      528      // A SMEM row stride bytes (33 x 16B, conflict-free ldmatrix)
#define HROW      264      // final fp32 hidden row stride (floats)

// SMEM layout (bytes)
#define SM_A     0                               // fp16 A image: 64 x 528 = 33792
#define SM_B     (SM_A + TM * AROW)              // 33792  (ring: 4 x 12288 = 49152)
#define SM_BIAS  (SM_B + NRING * CHUNK2)         // 82944  (4*256 floats)
#define SM_WOUT  (SM_BIAS + 4 * HD * 4)          // 87040  (3*256 floats)
#define SM_BOUT  (SM_WOUT + 3 * HD * 4)          // 90112  (4 floats)
#define SM_IDX   (SM_BOUT + 16)                  // 90128  (64 ints)
#define SMEM_BYTES (SM_IDX + TM * 4)             // 90384  (2 CTAs/SM fits easily)

// prep kernel block ranges
#define NB_SCAT  256
#define NB_MID   768      // 6144 mid rows / 8 warps
#define NB_WIN   256      // 2048 win rows / 8 warps
#define NB_WOUT  1
#define NB_PREP  (NB_SCAT + NB_MID + NB_WIN + NB_WOUT)

// ---------------- device scratch ----------------
__device__ float d_Wout[NC * NMID * HD];
__device__ __align__(512) unsigned char d_Wpk[NC * NKSTEP * CHUNK2];  // ~5.1 MB fp16 SMEM-image
__device__ int   d_sortedPad[NC * NMAX];
__device__ int   d_cursor[NC];
__device__ int   d_blkoff[NC + 1];

// ---------------- setup kernels ----------------
__global__ void initK() { if (threadIdx.x < NC) d_cursor[threadIdx.x] = 0; }

__global__ void prepK(const int* __restrict__ cid, int n,
                      const float* __restrict__ V_in,  const float* __restrict__ g_in,
                      const float* __restrict__ V_mid, const float* __restrict__ g_mid,
                      const float* __restrict__ V_out, const float* __restrict__ g_out) {
    const int blk  = blockIdx.x;
    const int tid  = threadIdx.x;
    const int wid  = tid >> 5;
    const int lane = tid & 31;

    if (blk < NB_SCAT) {
        __shared__ int lh[NC], base[NC];
        if (tid < NC) lh[tid] = 0;
        __syncthreads();
        int i = blk * 256 + tid;
        int c = -1, r = 0;
        if (i < n) { c = cid[i]; r = atomicAdd(&lh[c], 1); }
        __syncthreads();
        if (tid < NC) base[tid] = atomicAdd(&d_cursor[tid], lh[tid]);
        __syncthreads();
        if (i < n) d_sortedPad[c * NMAX + base[c] + r] = i;
        return;
    }
    if (blk < NB_SCAT + NB_MID) {
        // mid weights: norm + fp16 pack into SMEM-image chunks (ksteps 4..51)
        int row = (blk - NB_SCAT) * 8 + wid;         // [0, 6144)
        int c = row / (NMID * HD);
        int l = (row / HD) % NMID;
        int r = row & (HD - 1);
        const float* v = V_mid + (size_t)row * HD;
        float vals[8];
        float s = 0.f;
        #pragma unroll
        for (int j = 0; j < 8; j++) { vals[j] = v[lane + 32 * j]; s = fmaf(vals[j], vals[j], s); }
        #pragma unroll
        for (int off = 16; off; off >>= 1) s += __shfl_xor_sync(0xffffffffu, s, off);
        float scale = g_mid[row] * rsqrtf(s);
        #pragma unroll
        for (int j = 0; j < 8; j++) {
            int k = lane + 32 * j;
            int ks = 4 + l * 16 + (k >> 4);
            size_t ba = (size_t)(c * NKSTEP + ks) * CHUNK2 + (size_t)r * BROW2 + (size_t)(k & 15) * 2;
            *reinterpret_cast<__half*>(d_Wpk + ba) = __float2half(vals[j] * scale);
        }
        return;
    }
    if (blk < NB_SCAT + NB_MID + NB_WIN) {
        // layer-0 weights: norm + fp16 pack, K padded 36 -> 64 (kstep 3 stays zero-init)
        int row = (blk - NB_SCAT - NB_MID) * 8 + wid;   // [0, 2048)
        int c = row >> 8;
        int r = row & 255;
        const float* v = V_in + (size_t)row * DIN;
        float v0 = v[lane];
        float v1 = (lane < DIN - 32) ? v[32 + lane] : 0.f;
        float s = fmaf(v0, v0, v1 * v1);
        #pragma unroll
        for (int off = 16; off; off >>= 1) s += __shfl_xor_sync(0xffffffffu, s, off);
        float scale = g_in[row] * rsqrtf(s);
        #pragma unroll
        for (int half = 0; half < 2; half++) {
            int k = lane + 32 * half;
            if (k >= 48) continue;
            float w = (k < 32) ? v0 * scale : ((k < DIN) ? v1 * scale : 0.f);
            int ks = k >> 4;
            size_t ba = (size_t)(c * NKSTEP + ks) * CHUNK2 + (size_t)r * BROW2 + (size_t)(k & 15) * 2;
            *reinterpret_cast<__half*>(d_Wpk + ba) = __float2half(w);
        }
        return;
    }
    {
        #pragma unroll
        for (int it = 0; it < 3; it++) {
            int row = wid * 3 + it;                    // [0, 24)
            const float* v = V_out + (size_t)row * HD;
            float vals[8];
            float s = 0.f;
            #pragma unroll
            for (int j = 0; j < 8; j++) { vals[j] = v[lane + 32 * j]; s = fmaf(vals[j], vals[j], s); }
            #pragma unroll
            for (int off = 16; off; off >>= 1) s += __shfl_xor_sync(0xffffffffu, s, off);
            float scale = g_out[row] * rsqrtf(s);
            #pragma unroll
            for (int j = 0; j < 8; j++) d_Wout[row * HD + lane + 32 * j] = vals[j] * scale;
        }
    }
}

__global__ void prefixK() {
    if (threadIdx.x == 0) {
        int bo = 0;
        for (int c = 0; c < NC; c++) {
            d_blkoff[c] = bo;
            bo += (d_cursor[c] + TM - 1) / TM;
        }
        d_blkoff[NC] = bo;
    }
}

// ---------------- PTX helpers ----------------
__device__ __forceinline__ void cp16(uint32_t s, const void* g) {
    asm volatile("cp.async.cg.shared.global [%0], [%1], 16;" :: "r"(s), "l"(g));
}
__device__ __forceinline__ void cp_commit()  { asm volatile("cp.async.commit_group;"); }
__device__ __forceinline__ void cp_wait0()   { asm volatile("cp.async.wait_group 0;" ::: "memory"); }

__device__ __forceinline__ void ldsm4(uint32_t& r0, uint32_t& r1, uint32_t& r2, uint32_t& r3, uint32_t a) {
    asm volatile("ldmatrix.sync.aligned.m8n8.x4.shared.b16 {%0,%1,%2,%3}, [%4];"
                 : "=r"(r0), "=r"(r1), "=r"(r2), "=r"(r3) : "r"(a));
}

__device__ __forceinline__ void mma16816f(float* d, const uint32_t* a, uint32_t b0, uint32_t b1) {
    asm volatile("mma.sync.aligned.m16n8k16.row.col.f32.f16.f16.f32 "
                 "{%0,%1,%2,%3}, {%4,%5,%6,%7}, {%8,%9}, {%0,%1,%2,%3};"
                 : "+f"(d[0]), "+f"(d[1]), "+f"(d[2]), "+f"(d[3])
                 : "r"(a[0]), "r"(a[1]), "r"(a[2]), "r"(a[3]), "r"(b0), "r"(b1));
}

__device__ __forceinline__ uint32_t pack_h2(float a, float b) {
    __half2 h2 = __floats2half2_rn(a, b);
    return *reinterpret_cast<uint32_t*>(&h2);
}

// ---------------- fused MLP: all fp16 single-MMA, 4-slot ring, barrier per 2 ksteps ----------------
__global__ void __launch_bounds__(NTHR, 2)
mlpK(const float* __restrict__ X,
     const float* __restrict__ b_in,
     const float* __restrict__ b_mid,
     const float* __restrict__ b_out,
     float* __restrict__ out, int n) {
    extern __shared__ unsigned char smem[];

    int b = blockIdx.x;
    if (b >= d_blkoff[NC]) return;
    int c = 0;
    while (b >= d_blkoff[c + 1]) c++;
    const int start = (b - d_blkoff[c]) * TM;
    int cnt = d_cursor[c] - start;
    if (cnt > TM) cnt = TM;
    if (cnt < 0) cnt = 0;

    const int tid  = threadIdx.x;
    const int wid  = tid >> 5;
    const int lane = tid & 31;
    const int gid  = lane >> 2;
    const int tig  = lane & 3;
    const int sel  = lane >> 3;
    const int r8   = lane & 7;
    const uint32_t sbase = (uint32_t)__cvta_generic_to_shared(smem);

    float* biasS = (float*)(smem + SM_BIAS);
    float* WoutS = (float*)(smem + SM_WOUT);
    float* boutS = (float*)(smem + SM_BOUT);
    int*   idxS  = (int*)  (smem + SM_IDX);

    // ---- stage biases / Wout / bout ----
    #pragma unroll
    for (int it = 0; it < 4; it++) {
        int s = tid + it * NTHR;            // [0,1024)
        float v;
        if (s < HD) v = b_in[c * HD + s];
        else        v = b_mid[(c * NMID + (s / HD - 1)) * HD + (s & (HD - 1))];
        biasS[s] = v;
    }
    #pragma unroll
    for (int it = 0; it < 3; it++) {
        int s = tid + it * NTHR;
        WoutS[s] = d_Wout[c * NMID * HD + s];
    }
    if (tid < 3) boutS[tid] = b_out[c * NMID + tid];

    // ---- posenc -> fp16 A image (K padded to 64, cols 36..63 zero) ----
    if (tid < TM) {
        const int m = tid;
        const int id = (m < cnt) ? d_sortedPad[c * NMAX + start + m] : -1;
        idxS[m] = id;
        float e[36];
        #pragma unroll
        for (int k = 0; k < 36; k++) e[k] = 0.f;
        if (id >= 0) {
            float x = X[3 * id], y = X[3 * id + 1], z = X[3 * id + 2];
            float f = 1.f;
            #pragma unroll
            for (int fi = 0; fi < 6; fi++) {
                float s0, c0, s1, c1, s2, c2;
                sincosf(x * f, &s0, &c0);
                sincosf(y * f, &s1, &c1);
                sincosf(z * f, &s2, &c2);
                e[fi * 6 + 0] = s0; e[fi * 6 + 1] = s1; e[fi * 6 + 2] = s2;
                e[fi * 6 + 3] = c0; e[fi * 6 + 4] = c1; e[fi * 6 + 5] = c2;
                f *= 2.f;
            }
        }
        uint32_t* arow = (uint32_t*)(smem + SM_A + m * AROW);
        #pragma unroll
        for (int i = 0; i < 18; i++) arow[i] = pack_h2(e[2 * i], e[2 * i + 1]);
        #pragma unroll
        for (int i = 18; i < 32; i++) arow[i] = 0u;
    }

    // warp tiling: 2 (m) x 4 (n)
    const int m_base = (wid & 1) * 32;
    const int wn     = wid >> 1;
    const int n_base = wn * 64;

    uint32_t a_off[2];
    #pragma unroll
    for (int im = 0; im < 2; im++)
        a_off[im] = (uint32_t)((m_base + im * 16 + r8 + (sel & 1) * 8) * AROW + (sel >> 1) * 16);
    uint32_t bg_off[4];
    #pragma unroll
    for (int jg = 0; jg < 4; jg++)
        bg_off[jg] = (uint32_t)((n_base + jg * 16 + r8 + (sel >> 1) * 8) * BROW2 + (sel & 1) * 16);

    const unsigned char* wsrc = d_Wpk + (size_t)c * NKSTEP * CHUNK2;

    // prefetch ksteps 0,1 into ring slots 0,1 (one group)
    #pragma unroll
    for (int pc = 0; pc < 2; pc++) {
        const unsigned char* g = wsrc + (size_t)pc * CHUNK2;
        uint32_t sb = sbase + SM_B + pc * CHUNK2;
        #pragma unroll
        for (int j = 0; j < 3; j++) {
            int o = tid * 16 + j * 4096;
            cp16(sb + o, g + o);
        }
    }
    cp_commit();

    int q = 0;   // global kstep index

    #pragma unroll 1
    for (int l = 0; l < 4; l++) {
        float D[2][8][4];
        #pragma unroll
        for (int im = 0; im < 2; im++)
            #pragma unroll
            for (int jn = 0; jn < 8; jn++)
                #pragma unroll
                for (int e = 0; e < 4; e++) D[im][jn][e] = 0.f;

        const int nk = (l == 0) ? 4 : 16;
        #pragma unroll 1
        for (int t = 0; t < nk; t += 2) {
            // wait for ksteps q,q+1 data; barrier also protects ring slot reuse + A image
            cp_wait0();
            __syncthreads();

            // prefetch ksteps q+2,q+3 into slots consumed 2 iterations ago
            if (q + 2 < NKSTEP) {
                #pragma unroll
                for (int pc = 0; pc < 2; pc++) {
                    if (q + 2 + pc < NKSTEP) {
                        const unsigned char* g = wsrc + (size_t)(q + 2 + pc) * CHUNK2;
                        uint32_t sb = sbase + SM_B + ((q + 2 + pc) % NRING) * CHUNK2;
                        #pragma unroll
                        for (int j = 0; j < 3; j++) {
                            int o = tid * 16 + j * 4096;
                            cp16(sb + o, g + o);
                        }
                    }
                }
            }
            cp_commit();

            // ---- two ksteps of MMA ----
            #pragma unroll
            for (int u = 0; u < 2; u++) {
                const int qq = q + u;
                const uint32_t kbA = (uint32_t)(t + u) * 32;
                uint32_t A[2][4], Bf[4][4];
                #pragma unroll
                for (int im = 0; im < 2; im++)
                    ldsm4(A[im][0], A[im][1], A[im][2], A[im][3],
                          sbase + SM_A + a_off[im] + kbA);
                const uint32_t bA = sbase + SM_B + (uint32_t)(qq % NRING) * CHUNK2;
                #pragma unroll
                for (int jg = 0; jg < 4; jg++)
                    ldsm4(Bf[jg][0], Bf[jg][1], Bf[jg][2], Bf[jg][3], bA + bg_off[jg]);

                #pragma unroll
                for (int jg = 0; jg < 4; jg++)
                    #pragma unroll
                    for (int im = 0; im < 2; im++) {
                        mma16816f(D[im][jg * 2],     A[im], Bf[jg][0], Bf[jg][1]);
                        mma16816f(D[im][jg * 2 + 1], A[im], Bf[jg][2], Bf[jg][3]);
                    }
            }
            q += 2;
        }

        // ---- epilogue: barrier (all warps done reading A), rewrite A ----
        __syncthreads();
        const float* bias = biasS + l * HD;
        if (l < 3) {
            #pragma unroll
            for (int im = 0; im < 2; im++) {
                #pragma unroll
                for (int jn = 0; jn < 8; jn++) {
                    int ncol = n_base + jn * 8 + tig * 2;
                    float b0 = bias[ncol], b1 = bias[ncol + 1];
                    #pragma unroll
                    for (int h = 0; h < 2; h++) {
                        int m = m_base + im * 16 + gid + h * 8;
                        float v0 = fmaxf(D[im][jn][2 * h]     + b0, 0.f);
                        float v1 = fmaxf(D[im][jn][2 * h + 1] + b1, 0.f);
                        *(uint32_t*)(smem + SM_A + m * AROW + ncol * 2) = pack_h2(v0, v1);
                    }
                }
            }
        } else {
            // final hidden -> fp32 h across A+ring region (HROW floats per row)
            float* hbuf = (float*)(smem + SM_A);
            #pragma unroll
            for (int im = 0; im < 2; im++) {
                #pragma unroll
                for (int jn = 0; jn < 8; jn++) {
                    int ncol = n_base + jn * 8 + tig * 2;
                    float b0 = bias[ncol], b1 = bias[ncol + 1];
                    #pragma unroll
                    for (int h = 0; h < 2; h++) {
                        int m = m_base + im * 16 + gid + h * 8;
                        float v0 = fmaxf(D[im][jn][2 * h]     + b0, 0.f);
                        float v1 = fmaxf(D[im][jn][2 * h + 1] + b1, 0.f);
                        float2* p = (float2*)(hbuf + m * HROW + ncol);
                        *p = make_float2(v0, v1);
                    }
                }
            }
            __syncthreads();
            // fused output layer: 192 (m,j) dots of length 256
            const float* hb = (const float*)(smem + SM_A);
            #pragma unroll
            for (int qq = 0; qq < 24; qq++) {
                int o = wid * 24 + qq;
                int m = o / 3, j = o - 3 * m;
                const float* hr = hb + m * HROW;
                const float* wr = WoutS + j * HD;
                float s = 0.f;
                #pragma unroll
                for (int k = lane; k < HD; k += 32) s = fmaf(hr[k], wr[k], s);
                #pragma unroll
                for (int off = 16; off; off >>= 1) s += __shfl_xor_sync(0xffffffffu, s, off);
                if (lane == 0) {
                    int id = idxS[m];
                    if (id >= 0) out[3 * id + j] = tanhf(s + boutS[j]);
                }
            }
        }
    }
}

// ---------------- launch ----------------
extern "C" void kernel_launch(void* const* d_in, const int* in_sizes, int n_in,
                              void* d_out, int out_size) {
    const float* X     = (const float*)d_in[0];
    const int*   cid   = (const int*)  d_in[1];
    const float* V_in  = (const float*)d_in[2];
    const float* g_in  = (const float*)d_in[3];
    const float* b_in  = (const float*)d_in[4];
    const float* V_mid = (const float*)d_in[5];
    const float* g_mid = (const float*)d_in[6];
    const float* b_mid = (const float*)d_in[7];
    const float* V_out = (const float*)d_in[8];
    const float* g_out = (const float*)d_in[9];
    const float* b_out = (const float*)d_in[10];
    float* out = (float*)d_out;
    const int n = in_sizes[0] / 3;

    cudaFuncSetAttribute(mlpK, cudaFuncAttributeMaxDynamicSharedMemorySize, SMEM_BYTES);

    initK<<<1, 32>>>();
    prepK<<<NB_PREP, 256>>>(cid, n, V_in, g_in, V_mid, g_mid, V_out, g_out);
    prefixK<<<1, 1>>>();

    const int blocks = (n + TM - 1) / TM + NC;
    mlpK<<<blocks, NTHR, SMEM_BYTES>>>(X, b_in, b_mid, b_out, out, n);
}

// round 13
// speedup vs baseline: 2.8776x; 1.0593x over previous
#include <cuda_runtime.h>
#include <cuda_fp16.h>
#include <math.h>
#include <stdint.h>

// ---------------- problem constants ----------------
#define NC    8
#define HD    256
#define DIN   36
#define NMID  3
#define NMAX  65536
#define TM    64           // points per CTA
#define NTHR  256          // 8 warps: 2 (m) x 4 (n)

#define BROW2     32       // chunk row stride bytes (16 fp16, XOR-swizzled -> conflict-free)
#define CHUNK2    8192     // 256 rows x 32B: one kstep of fp16 weights
#define NRING     8        // ring slots (power of 2)
#define GK        4        // ksteps per barrier group
#define NKSTEP    52       // 4 (layer0 K=64 padded) + 3*16 (mid layers K=256)
#define AROW      528      // A SMEM row stride bytes (33 x 16B, conflict-free ldmatrix)
#define HROW      264      // final fp32 hidden row stride (floats)

// SMEM layout (bytes)
#define SM_A     0                               // fp16 A image: 64 x 528 = 33792
#define SM_B     (SM_A + TM * AROW)              // 33792  (ring: 8 x 8192 = 65536)
#define SM_BIAS  (SM_B + NRING * CHUNK2)         // 99328  (4*256 floats)
#define SM_WOUT  (SM_BIAS + 4 * HD * 4)          // 103424 (3*256 floats)
#define SM_BOUT  (SM_WOUT + 3 * HD * 4)          // 106496 (4 floats)
#define SM_IDX   (SM_BOUT + 16)                  // 106512 (64 ints)
#define SMEM_BYTES (SM_IDX + TM * 4)             // 106768 (2 CTAs/SM: 213.5KB <= 228KB)

// prep kernel block ranges
#define NB_SCAT  256
#define NB_MID   768      // 6144 mid rows / 8 warps
#define NB_WIN   256      // 2048 win rows / 8 warps
#define NB_WOUT  1
#define NB_PREP  (NB_SCAT + NB_MID + NB_WIN + NB_WOUT)

// ---------------- device scratch ----------------
__device__ float d_Wout[NC * NMID * HD];
__device__ __align__(512) unsigned char d_Wpk[NC * NKSTEP * CHUNK2];  // ~3.4 MB fp16 swizzled
__device__ int   d_sortedPad[NC * NMAX];
__device__ int   d_cursor[NC];
__device__ int   d_blkoff[NC + 1];

// swizzled in-chunk byte offset for (row r, k in [0,16))
__device__ __forceinline__ size_t wswz(int r, int k) {
    int k16 = (k >> 3) & 1;
    int sw  = k16 ^ ((r >> 2) & 1);
    return (size_t)r * BROW2 + (size_t)(sw << 4) + (size_t)(k & 7) * 2;
}

// ---------------- setup kernels ----------------
__global__ void initK() { if (threadIdx.x < NC) d_cursor[threadIdx.x] = 0; }

__global__ void prepK(const int* __restrict__ cid, int n,
                      const float* __restrict__ V_in,  const float* __restrict__ g_in,
                      const float* __restrict__ V_mid, const float* __restrict__ g_mid,
                      const float* __restrict__ V_out, const float* __restrict__ g_out) {
    const int blk  = blockIdx.x;
    const int tid  = threadIdx.x;
    const int wid  = tid >> 5;
    const int lane = tid & 31;

    if (blk < NB_SCAT) {
        __shared__ int lh[NC], base[NC];
        if (tid < NC) lh[tid] = 0;
        __syncthreads();
        int i = blk * 256 + tid;
        int c = -1, r = 0;
        if (i < n) { c = cid[i]; r = atomicAdd(&lh[c], 1); }
        __syncthreads();
        if (tid < NC) base[tid] = atomicAdd(&d_cursor[tid], lh[tid]);
        __syncthreads();
        if (i < n) d_sortedPad[c * NMAX + base[c] + r] = i;
        return;
    }
    if (blk < NB_SCAT + NB_MID) {
        // mid weights: norm + fp16 pack into swizzled chunks (ksteps 4..51)
        int row = (blk - NB_SCAT) * 8 + wid;         // [0, 6144)
        int c = row / (NMID * HD);
        int l = (row / HD) % NMID;
        int r = row & (HD - 1);
        const float* v = V_mid + (size_t)row * HD;
        float vals[8];
        float s = 0.f;
        #pragma unroll
        for (int j = 0; j < 8; j++) { vals[j] = v[lane + 32 * j]; s = fmaf(vals[j], vals[j], s); }
        #pragma unroll
        for (int off = 16; off; off >>= 1) s += __shfl_xor_sync(0xffffffffu, s, off);
        float scale = g_mid[row] * rsqrtf(s);
        #pragma unroll
        for (int j = 0; j < 8; j++) {
            int k = lane + 32 * j;
            int ks = 4 + l * 16 + (k >> 4);
            size_t ba = (size_t)(c * NKSTEP + ks) * CHUNK2 + wswz(r, k & 15);
            *reinterpret_cast<__half*>(d_Wpk + ba) = __float2half(vals[j] * scale);
        }
        return;
    }
    if (blk < NB_SCAT + NB_MID + NB_WIN) {
        // layer-0 weights: norm + fp16 pack, K padded 36 -> 64 (kstep 3 stays zero-init)
        int row = (blk - NB_SCAT - NB_MID) * 8 + wid;   // [0, 2048)
        int c = row >> 8;
        int r = row & 255;
        const float* v = V_in + (size_t)row * DIN;
        float v0 = v[lane];
        float v1 = (lane < DIN - 32) ? v[32 + lane] : 0.f;
        float s = fmaf(v0, v0, v1 * v1);
        #pragma unroll
        for (int off = 16; off; off >>= 1) s += __shfl_xor_sync(0xffffffffu, s, off);
        float scale = g_in[row] * rsqrtf(s);
        #pragma unroll
        for (int half = 0; half < 2; half++) {
            int k = lane + 32 * half;
            if (k >= 48) continue;
            float w = (k < 32) ? v0 * scale : ((k < DIN) ? v1 * scale : 0.f);
            int ks = k >> 4;
            size_t ba = (size_t)(c * NKSTEP + ks) * CHUNK2 + wswz(r, k & 15);
            *reinterpret_cast<__half*>(d_Wpk + ba) = __float2half(w);
        }
        return;
    }
    {
        #pragma unroll
        for (int it = 0; it < 3; it++) {
            int row = wid * 3 + it;                    // [0, 24)
            const float* v = V_out + (size_t)row * HD;
            float vals[8];
            float s = 0.f;
            #pragma unroll
            for (int j = 0; j < 8; j++) { vals[j] = v[lane + 32 * j]; s = fmaf(vals[j], vals[j], s); }
            #pragma unroll
            for (int off = 16; off; off >>= 1) s += __shfl_xor_sync(0xffffffffu, s, off);
            float scale = g_out[row] * rsqrtf(s);
            #pragma unroll
            for (int j = 0; j < 8; j++) d_Wout[row * HD + lane + 32 * j] = vals[j] * scale;
        }
    }
}

__global__ void prefixK() {
    if (threadIdx.x == 0) {
        int bo = 0;
        for (int c = 0; c < NC; c++) {
            d_blkoff[c] = bo;
            bo += (d_cursor[c] + TM - 1) / TM;
        }
        d_blkoff[NC] = bo;
    }
}

// ---------------- PTX helpers ----------------
__device__ __forceinline__ void cp16(uint32_t s, const void* g) {
    asm volatile("cp.async.cg.shared.global [%0], [%1], 16;" :: "r"(s), "l"(g));
}
__device__ __forceinline__ void cp_commit()  { asm volatile("cp.async.commit_group;"); }
__device__ __forceinline__ void cp_wait0()   { asm volatile("cp.async.wait_group 0;" ::: "memory"); }

__device__ __forceinline__ void ldsm4(uint32_t& r0, uint32_t& r1, uint32_t& r2, uint32_t& r3, uint32_t a) {
    asm volatile("ldmatrix.sync.aligned.m8n8.x4.shared.b16 {%0,%1,%2,%3}, [%4];"
                 : "=r"(r0), "=r"(r1), "=r"(r2), "=r"(r3) : "r"(a));
}

__device__ __forceinline__ void mma16816f(float* d, const uint32_t* a, uint32_t b0, uint32_t b1) {
    asm volatile("mma.sync.aligned.m16n8k16.row.col.f32.f16.f16.f32 "
                 "{%0,%1,%2,%3}, {%4,%5,%6,%7}, {%8,%9}, {%0,%1,%2,%3};"
                 : "+f"(d[0]), "+f"(d[1]), "+f"(d[2]), "+f"(d[3])
                 : "r"(a[0]), "r"(a[1]), "r"(a[2]), "r"(a[3]), "r"(b0), "r"(b1));
}

__device__ __forceinline__ uint32_t pack_h2(float a, float b) {
    __half2 h2 = __floats2half2_rn(a, b);
    return *reinterpret_cast<uint32_t*>(&h2);
}

// ---------------- fused MLP: fp16 single-MMA, 8-slot ring, barrier per 4 ksteps ----------------
__global__ void __launch_bounds__(NTHR, 2)
mlpK(const float* __restrict__ X,
     const float* __restrict__ b_in,
     const float* __restrict__ b_mid,
     const float* __restrict__ b_out,
     float* __restrict__ out, int n) {
    extern __shared__ unsigned char smem[];

    int b = blockIdx.x;
    if (b >= d_blkoff[NC]) return;
    int c = 0;
    while (b >= d_blkoff[c + 1]) c++;
    const int start = (b - d_blkoff[c]) * TM;
    int cnt = d_cursor[c] - start;
    if (cnt > TM) cnt = TM;
    if (cnt < 0) cnt = 0;

    const int tid  = threadIdx.x;
    const int wid  = tid >> 5;
    const int lane = tid & 31;
    const int gid  = lane >> 2;
    const int tig  = lane & 3;
    const int sel  = lane >> 3;
    const int r8   = lane & 7;
    const uint32_t sbase = (uint32_t)__cvta_generic_to_shared(smem);

    float* biasS = (float*)(smem + SM_BIAS);
    float* WoutS = (float*)(smem + SM_WOUT);
    float* boutS = (float*)(smem + SM_BOUT);
    int*   idxS  = (int*)  (smem + SM_IDX);

    // ---- stage biases / Wout / bout ----
    #pragma unroll
    for (int it = 0; it < 4; it++) {
        int s = tid + it * NTHR;            // [0,1024)
        float v;
        if (s < HD) v = b_in[c * HD + s];
        else        v = b_mid[(c * NMID + (s / HD - 1)) * HD + (s & (HD - 1))];
        biasS[s] = v;
    }
    #pragma unroll
    for (int it = 0; it < 3; it++) {
        int s = tid + it * NTHR;
        WoutS[s] = d_Wout[c * NMID * HD + s];
    }
    if (tid < 3) boutS[tid] = b_out[c * NMID + tid];

    // ---- posenc -> fp16 A image (K padded to 64, cols 36..63 zero) ----
    if (tid < TM) {
        const int m = tid;
        const int id = (m < cnt) ? d_sortedPad[c * NMAX + start + m] : -1;
        idxS[m] = id;
        float e[36];
        #pragma unroll
        for (int k = 0; k < 36; k++) e[k] = 0.f;
        if (id >= 0) {
            float x = X[3 * id], y = X[3 * id + 1], z = X[3 * id + 2];
            float f = 1.f;
            #pragma unroll
            for (int fi = 0; fi < 6; fi++) {
                float s0, c0, s1, c1, s2, c2;
                sincosf(x * f, &s0, &c0);
                sincosf(y * f, &s1, &c1);
                sincosf(z * f, &s2, &c2);
                e[fi * 6 + 0] = s0; e[fi * 6 + 1] = s1; e[fi * 6 + 2] = s2;
                e[fi * 6 + 3] = c0; e[fi * 6 + 4] = c1; e[fi * 6 + 5] = c2;
                f *= 2.f;
            }
        }
        uint32_t* arow = (uint32_t*)(smem + SM_A + m * AROW);
        #pragma unroll
        for (int i = 0; i < 18; i++) arow[i] = pack_h2(e[2 * i], e[2 * i + 1]);
        #pragma unroll
        for (int i = 18; i < 32; i++) arow[i] = 0u;
    }

    // warp tiling: 2 (m) x 4 (n)
    const int m_base = (wid & 1) * 32;
    const int wn     = wid >> 1;
    const int n_base = wn * 64;

    uint32_t a_off[2];
    #pragma unroll
    for (int im = 0; im < 2; im++)
        a_off[im] = (uint32_t)((m_base + im * 16 + r8 + (sel & 1) * 8) * AROW + (sel >> 1) * 16);
    // B ldsm offsets with XOR swizzle on the 16B selector
    uint32_t bg_off[4];
    #pragma unroll
    for (int jg = 0; jg < 4; jg++) {
        int row = n_base + jg * 16 + (sel >> 1) * 8 + r8;
        int sw  = (sel & 1) ^ ((r8 >> 2) & 1);
        bg_off[jg] = (uint32_t)(row * BROW2 + sw * 16);
    }

    const unsigned char* wsrc = d_Wpk + (size_t)c * NKSTEP * CHUNK2;

    // prefetch group 0 (ksteps 0..3) into ring slots 0..3
    #pragma unroll
    for (int pc = 0; pc < GK; pc++) {
        const unsigned char* g = wsrc + (size_t)pc * CHUNK2;
        uint32_t sb = sbase + SM_B + pc * CHUNK2;
        #pragma unroll
        for (int j = 0; j < 2; j++) {
            int o = tid * 16 + j * 4096;
            cp16(sb + o, g + o);
        }
    }
    cp_commit();

    int q = 0;   // global kstep index

    #pragma unroll 1
    for (int l = 0; l < 4; l++) {
        float D[2][8][4];
        #pragma unroll
        for (int im = 0; im < 2; im++)
            #pragma unroll
            for (int jn = 0; jn < 8; jn++)
                #pragma unroll
                for (int e = 0; e < 4; e++) D[im][jn][e] = 0.f;

        const int nk = (l == 0) ? 4 : 16;
        #pragma unroll 1
        for (int t = 0; t < nk; t += GK) {
            // wait for current group's data; barrier protects ring reuse + A image
            cp_wait0();
            __syncthreads();

            // prefetch next group (ksteps q+GK .. q+2GK-1)
            #pragma unroll
            for (int pc = 0; pc < GK; pc++) {
                int nq = q + GK + pc;
                if (nq < NKSTEP) {
                    const unsigned char* g = wsrc + (size_t)nq * CHUNK2;
                    uint32_t sb = sbase + SM_B + (nq & (NRING - 1)) * CHUNK2;
                    #pragma unroll
                    for (int j = 0; j < 2; j++) {
                        int o = tid * 16 + j * 4096;
                        cp16(sb + o, g + o);
                    }
                }
            }
            cp_commit();

            // ---- GK ksteps of MMA ----
            #pragma unroll
            for (int u = 0; u < GK; u++) {
                const int qq = q + u;
                const uint32_t kbA = (uint32_t)(t + u) * 32;
                uint32_t A[2][4], Bf[4][4];
                #pragma unroll
                for (int im = 0; im < 2; im++)
                    ldsm4(A[im][0], A[im][1], A[im][2], A[im][3],
                          sbase + SM_A + a_off[im] + kbA);
                const uint32_t bA = sbase + SM_B + (uint32_t)(qq & (NRING - 1)) * CHUNK2;
                #pragma unroll
                for (int jg = 0; jg < 4; jg++)
                    ldsm4(Bf[jg][0], Bf[jg][1], Bf[jg][2], Bf[jg][3], bA + bg_off[jg]);

                #pragma unroll
                for (int jg = 0; jg < 4; jg++)
                    #pragma unroll
                    for (int im = 0; im < 2; im++) {
                        mma16816f(D[im][jg * 2],     A[im], Bf[jg][0], Bf[jg][1]);
                        mma16816f(D[im][jg * 2 + 1], A[im], Bf[jg][2], Bf[jg][3]);
                    }
            }
            q += GK;
        }

        // ---- epilogue: barrier (all warps done reading A), rewrite A ----
        __syncthreads();
        const float* bias = biasS + l * HD;
        if (l < 3) {
            #pragma unroll
            for (int im = 0; im < 2; im++) {
                #pragma unroll
                for (int jn = 0; jn < 8; jn++) {
                    int ncol = n_base + jn * 8 + tig * 2;
                    float b0 = bias[ncol], b1 = bias[ncol + 1];
                    #pragma unroll
                    for (int h = 0; h < 2; h++) {
                        int m = m_base + im * 16 + gid + h * 8;
                        float v0 = fmaxf(D[im][jn][2 * h]     + b0, 0.f);
                        float v1 = fmaxf(D[im][jn][2 * h + 1] + b1, 0.f);
                        *(uint32_t*)(smem + SM_A + m * AROW + ncol * 2) = pack_h2(v0, v1);
                    }
                }
            }
        } else {
            // final hidden -> fp32 h across A+ring region (HROW floats per row)
            float* hbuf = (float*)(smem + SM_A);
            #pragma unroll
            for (int im = 0; im < 2; im++) {
                #pragma unroll
                for (int jn = 0; jn < 8; jn++) {
                    int ncol = n_base + jn * 8 + tig * 2;
                    float b0 = bias[ncol], b1 = bias[ncol + 1];
                    #pragma unroll
                    for (int h = 0; h < 2; h++) {
                        int m = m_base + im * 16 + gid + h * 8;
                        float v0 = fmaxf(D[im][jn][2 * h]     + b0, 0.f);
                        float v1 = fmaxf(D[im][jn][2 * h + 1] + b1, 0.f);
                        float2* p = (float2*)(hbuf + m * HROW + ncol);
                        *p = make_float2(v0, v1);
                    }
                }
            }
            __syncthreads();
            // fused output layer: 192 (m,j) dots of length 256
            const float* hb = (const float*)(smem + SM_A);
            #pragma unroll
            for (int qq = 0; qq < 24; qq++) {
                int o = wid * 24 + qq;
                int m = o / 3, j = o - 3 * m;
                const float* hr = hb + m * HROW;
                const float* wr = WoutS + j * HD;
                float s = 0.f;
                #pragma unroll
                for (int k = lane; k < HD; k += 32) s = fmaf(hr[k], wr[k], s);
                #pragma unroll
                for (int off = 16; off; off >>= 1) s += __shfl_xor_sync(0xffffffffu, s, off);
                if (lane == 0) {
                    int id = idxS[m];
                    if (id >= 0) out[3 * id + j] = tanhf(s + boutS[j]);
                }
            }
        }
    }
}

// ---------------- launch ----------------
extern "C" void kernel_launch(void* const* d_in, const int* in_sizes, int n_in,
                              void* d_out, int out_size) {
    const float* X     = (const float*)d_in[0];
    const int*   cid   = (const int*)  d_in[1];
    const float* V_in  = (const float*)d_in[2];
    const float* g_in  = (const float*)d_in[3];
    const float* b_in  = (const float*)d_in[4];
    const float* V_mid = (const float*)d_in[5];
    const float* g_mid = (const float*)d_in[6];
    const float* b_mid = (const float*)d_in[7];
    const float* V_out = (const float*)d_in[8];
    const float* g_out = (const float*)d_in[9];
    const float* b_out = (const float*)d_in[10];
    float* out = (float*)d_out;
    const int n = in_sizes[0] / 3;

    cudaFuncSetAttribute(mlpK, cudaFuncAttributeMaxDynamicSharedMemorySize, SMEM_BYTES);

    initK<<<1, 32>>>();
    prepK<<<NB_PREP, 256>>>(cid, n, V_in, g_in, V_mid, g_mid, V_out, g_out);
    prefixK<<<1, 1>>>();

    const int blocks = (n + TM - 1) / TM + NC;
    mlpK<<<blocks, NTHR, SMEM_BYTES>>>(X, b_in, b_mid, b_out, out, n);
}